// round 9
// baseline (speedup 1.0000x reference)
#include <cuda_runtime.h>

// out[b] = dot(user_factors[users[b]], item_factors[items[b]]), D = 64, fp32.
//
// 256 CTAs x 256 threads, 8 elements per warp (best-measured shape).
//  - Index stage: 4x LDG.128 (int4) instead of 8x LDG.32 (uniform -> broadcast).
//  - 8 front-batched warp-wide LDG.128 row loads: 16 lanes cover one 64-float
//    row, each load fetches TWO rows (elements 2p and 2p+1). MLP=8.
//  - 32-bit byte-offset address math (tables < 256 MB): no IMAD.WIDE on the
//    idx -> address -> LDG critical chain.
//  - 4 interleaved 16-lane butterfly reductions + one cross-half exchange,
//    then TWO STG.128 per warp (lanes 0 and 16) instead of 8 STG.32.

#define D 64
#define ROW_BYTES 256u
#define ELEMS_PER_WARP 8
#define WARPS_PER_BLOCK 8
#define THREADS (WARPS_PER_BLOCK * 32)

__global__ __launch_bounds__(THREADS)
void mf_dot_kernel(const int* __restrict__ users,
                   const int* __restrict__ items,
                   const float* __restrict__ user_factors,
                   const float* __restrict__ item_factors,
                   float* __restrict__ out)
{
    const int warp_id = (blockIdx.x * WARPS_PER_BLOCK) + (threadIdx.x >> 5);
    const int lane = threadIdx.x & 31;
    const int half = lane >> 4;               // 0: even element of pair, 1: odd
    const unsigned sub16 = (lane & 15) * 16u; // byte offset of this lane's float4
    const int base = warp_id * ELEMS_PER_WARP;

    const char* ubase = reinterpret_cast<const char*>(user_factors);
    const char* vbase = reinterpret_cast<const char*>(item_factors);

    // ---- Stage 1: vectorized index loads (4x LDG.128, warp-uniform) ----
    int4 ulo = __ldg(reinterpret_cast<const int4*>(users + base));      // elems 0..3
    int4 uhi = __ldg(reinterpret_cast<const int4*>(users + base + 4));  // elems 4..7
    int4 ilo = __ldg(reinterpret_cast<const int4*>(items + base));
    int4 ihi = __ldg(reinterpret_cast<const int4*>(items + base + 4));

    // Pair p serves element (2p + half).
    unsigned uidx0 = (unsigned)(half ? ulo.y : ulo.x);   // elem 0/1
    unsigned iidx0 = (unsigned)(half ? ilo.y : ilo.x);
    unsigned uidx1 = (unsigned)(half ? ulo.w : ulo.z);   // elem 2/3
    unsigned iidx1 = (unsigned)(half ? ilo.w : ilo.z);
    unsigned uidx2 = (unsigned)(half ? uhi.y : uhi.x);   // elem 4/5
    unsigned iidx2 = (unsigned)(half ? ihi.y : ihi.x);
    unsigned uidx3 = (unsigned)(half ? uhi.w : uhi.z);   // elem 6/7
    unsigned iidx3 = (unsigned)(half ? ihi.w : ihi.z);

    // ---- Stage 2: 8 independent LDG.128 row loads (32-bit offsets) ----
    float4 a0 = __ldg(reinterpret_cast<const float4*>(ubase + uidx0 * ROW_BYTES + sub16));
    float4 b0 = __ldg(reinterpret_cast<const float4*>(vbase + iidx0 * ROW_BYTES + sub16));
    float4 a1 = __ldg(reinterpret_cast<const float4*>(ubase + uidx1 * ROW_BYTES + sub16));
    float4 b1 = __ldg(reinterpret_cast<const float4*>(vbase + iidx1 * ROW_BYTES + sub16));
    float4 a2 = __ldg(reinterpret_cast<const float4*>(ubase + uidx2 * ROW_BYTES + sub16));
    float4 b2 = __ldg(reinterpret_cast<const float4*>(vbase + iidx2 * ROW_BYTES + sub16));
    float4 a3 = __ldg(reinterpret_cast<const float4*>(ubase + uidx3 * ROW_BYTES + sub16));
    float4 b3 = __ldg(reinterpret_cast<const float4*>(vbase + iidx3 * ROW_BYTES + sub16));

    // ---- Stage 3: per-lane dot4, then 4 interleaved 16-lane reductions ----
    float acc0 = a0.x * b0.x;
    acc0 = fmaf(a0.y, b0.y, acc0); acc0 = fmaf(a0.z, b0.z, acc0); acc0 = fmaf(a0.w, b0.w, acc0);
    float acc1 = a1.x * b1.x;
    acc1 = fmaf(a1.y, b1.y, acc1); acc1 = fmaf(a1.z, b1.z, acc1); acc1 = fmaf(a1.w, b1.w, acc1);
    float acc2 = a2.x * b2.x;
    acc2 = fmaf(a2.y, b2.y, acc2); acc2 = fmaf(a2.z, b2.z, acc2); acc2 = fmaf(a2.w, b2.w, acc2);
    float acc3 = a3.x * b3.x;
    acc3 = fmaf(a3.y, b3.y, acc3); acc3 = fmaf(a3.z, b3.z, acc3); acc3 = fmaf(a3.w, b3.w, acc3);

    #pragma unroll
    for (int off = 8; off > 0; off >>= 1) {
        acc0 += __shfl_xor_sync(0xFFFFFFFFu, acc0, off);
        acc1 += __shfl_xor_sync(0xFFFFFFFFu, acc1, off);
        acc2 += __shfl_xor_sync(0xFFFFFFFFu, acc2, off);
        acc3 += __shfl_xor_sync(0xFFFFFFFFu, acc3, off);
    }

    // ---- Stage 4: cross-half exchange, then 2x STG.128 per warp ----
    // After the butterfly, every lane in half h holds the reduced value for
    // elements {2p + h}. Exchange across halves so lane 0 can store elements
    // 0..3 and lane 16 elements 4..7 as single float4 stores.
    float o0 = __shfl_xor_sync(0xFFFFFFFFu, acc0, 16);  // other half's pair-0 result
    float o1 = __shfl_xor_sync(0xFFFFFFFFu, acc1, 16);
    float o2 = __shfl_xor_sync(0xFFFFFFFFu, acc2, 16);
    float o3 = __shfl_xor_sync(0xFFFFFFFFu, acc3, 16);

    if (lane == 0) {
        // half 0: acc_p = even elems, o_p = odd elems.
        float4 r = make_float4(acc0, o0, acc1, o1);      // elems 0,1,2,3
        *reinterpret_cast<float4*>(out + base) = r;
    } else if (lane == 16) {
        // half 1: o_p = even elems, acc_p = odd elems.
        float4 r = make_float4(o2, acc2, o3, acc3);      // elems 4,5,6,7
        *reinterpret_cast<float4*>(out + base + 4) = r;
    }
}

extern "C" void kernel_launch(void* const* d_in, const int* in_sizes, int n_in,
                              void* d_out, int out_size)
{
    const int*   users        = (const int*)  d_in[0];
    const int*   items        = (const int*)  d_in[1];
    const float* user_factors = (const float*)d_in[2];
    const float* item_factors = (const float*)d_in[3];
    float*       out          = (float*)      d_out;

    int batch = in_sizes[0];                       // 16384
    int warps = batch / ELEMS_PER_WARP;            // 2048
    int blocks = warps / WARPS_PER_BLOCK;          // 256
    mf_dot_kernel<<<blocks, THREADS>>>(users, items, user_factors, item_factors, out);
}

// round 10
// speedup vs baseline: 1.0049x; 1.0049x over previous
#include <cuda_runtime.h>

// out[b] = dot(user_factors[users[b]], item_factors[items[b]]), D = 64, fp32.
//
// 512 CTAs x 128 threads (2048 warps), 8 elements per warp.
//  - Index stage: 4x LDG.128 (int4), warp-uniform -> L1 broadcast.
//  - 8 front-batched warp-wide LDG.128 row loads: 16 lanes cover one 64-float
//    row, each load fetches TWO rows (elements 2p and 2p+1). MLP=8.
//  - 32-bit byte-offset address math (tables < 256 MB): no IMAD.WIDE on the
//    idx -> address -> LDG critical chain.
//  - 4 interleaved 16-lane butterfly reductions + one cross-half exchange,
//    then TWO STG.128 per warp (lanes 0 and 16).
//  - Small CTAs (4 warps) shrink per-CTA ramp/drain quanta; no __syncthreads
//    anywhere, so CTA size is purely a scheduling-granularity knob.

#define D 64
#define ROW_BYTES 256u
#define ELEMS_PER_WARP 8
#define WARPS_PER_BLOCK 4
#define THREADS (WARPS_PER_BLOCK * 32)

__global__ __launch_bounds__(THREADS)
void mf_dot_kernel(const int* __restrict__ users,
                   const int* __restrict__ items,
                   const float* __restrict__ user_factors,
                   const float* __restrict__ item_factors,
                   float* __restrict__ out)
{
    const int warp_id = (blockIdx.x * WARPS_PER_BLOCK) + (threadIdx.x >> 5);
    const int lane = threadIdx.x & 31;
    const int half = lane >> 4;               // 0: even element of pair, 1: odd
    const unsigned sub16 = (lane & 15) * 16u; // byte offset of this lane's float4
    const int base = warp_id * ELEMS_PER_WARP;

    const char* ubase = reinterpret_cast<const char*>(user_factors);
    const char* vbase = reinterpret_cast<const char*>(item_factors);

    // ---- Stage 1: vectorized index loads (4x LDG.128, warp-uniform) ----
    int4 ulo = __ldg(reinterpret_cast<const int4*>(users + base));      // elems 0..3
    int4 uhi = __ldg(reinterpret_cast<const int4*>(users + base + 4));  // elems 4..7
    int4 ilo = __ldg(reinterpret_cast<const int4*>(items + base));
    int4 ihi = __ldg(reinterpret_cast<const int4*>(items + base + 4));

    // Pair p serves element (2p + half).
    unsigned uidx0 = (unsigned)(half ? ulo.y : ulo.x);   // elem 0/1
    unsigned iidx0 = (unsigned)(half ? ilo.y : ilo.x);
    unsigned uidx1 = (unsigned)(half ? ulo.w : ulo.z);   // elem 2/3
    unsigned iidx1 = (unsigned)(half ? ilo.w : ilo.z);
    unsigned uidx2 = (unsigned)(half ? uhi.y : uhi.x);   // elem 4/5
    unsigned iidx2 = (unsigned)(half ? ihi.y : ihi.x);
    unsigned uidx3 = (unsigned)(half ? uhi.w : uhi.z);   // elem 6/7
    unsigned iidx3 = (unsigned)(half ? ihi.w : ihi.z);

    // ---- Stage 2: 8 independent LDG.128 row loads (32-bit offsets) ----
    float4 a0 = __ldg(reinterpret_cast<const float4*>(ubase + uidx0 * ROW_BYTES + sub16));
    float4 b0 = __ldg(reinterpret_cast<const float4*>(vbase + iidx0 * ROW_BYTES + sub16));
    float4 a1 = __ldg(reinterpret_cast<const float4*>(ubase + uidx1 * ROW_BYTES + sub16));
    float4 b1 = __ldg(reinterpret_cast<const float4*>(vbase + iidx1 * ROW_BYTES + sub16));
    float4 a2 = __ldg(reinterpret_cast<const float4*>(ubase + uidx2 * ROW_BYTES + sub16));
    float4 b2 = __ldg(reinterpret_cast<const float4*>(vbase + iidx2 * ROW_BYTES + sub16));
    float4 a3 = __ldg(reinterpret_cast<const float4*>(ubase + uidx3 * ROW_BYTES + sub16));
    float4 b3 = __ldg(reinterpret_cast<const float4*>(vbase + iidx3 * ROW_BYTES + sub16));

    // ---- Stage 3: per-lane dot4, then 4 interleaved 16-lane reductions ----
    float acc0 = a0.x * b0.x;
    acc0 = fmaf(a0.y, b0.y, acc0); acc0 = fmaf(a0.z, b0.z, acc0); acc0 = fmaf(a0.w, b0.w, acc0);
    float acc1 = a1.x * b1.x;
    acc1 = fmaf(a1.y, b1.y, acc1); acc1 = fmaf(a1.z, b1.z, acc1); acc1 = fmaf(a1.w, b1.w, acc1);
    float acc2 = a2.x * b2.x;
    acc2 = fmaf(a2.y, b2.y, acc2); acc2 = fmaf(a2.z, b2.z, acc2); acc2 = fmaf(a2.w, b2.w, acc2);
    float acc3 = a3.x * b3.x;
    acc3 = fmaf(a3.y, b3.y, acc3); acc3 = fmaf(a3.z, b3.z, acc3); acc3 = fmaf(a3.w, b3.w, acc3);

    #pragma unroll
    for (int off = 8; off > 0; off >>= 1) {
        acc0 += __shfl_xor_sync(0xFFFFFFFFu, acc0, off);
        acc1 += __shfl_xor_sync(0xFFFFFFFFu, acc1, off);
        acc2 += __shfl_xor_sync(0xFFFFFFFFu, acc2, off);
        acc3 += __shfl_xor_sync(0xFFFFFFFFu, acc3, off);
    }

    // ---- Stage 4: cross-half exchange, then 2x STG.128 per warp ----
    float o0 = __shfl_xor_sync(0xFFFFFFFFu, acc0, 16);
    float o1 = __shfl_xor_sync(0xFFFFFFFFu, acc1, 16);
    float o2 = __shfl_xor_sync(0xFFFFFFFFu, acc2, 16);
    float o3 = __shfl_xor_sync(0xFFFFFFFFu, acc3, 16);

    if (lane == 0) {
        float4 r = make_float4(acc0, o0, acc1, o1);      // elems 0,1,2,3
        *reinterpret_cast<float4*>(out + base) = r;
    } else if (lane == 16) {
        float4 r = make_float4(o2, acc2, o3, acc3);      // elems 4,5,6,7
        *reinterpret_cast<float4*>(out + base + 4) = r;
    }
}

extern "C" void kernel_launch(void* const* d_in, const int* in_sizes, int n_in,
                              void* d_out, int out_size)
{
    const int*   users        = (const int*)  d_in[0];
    const int*   items        = (const int*)  d_in[1];
    const float* user_factors = (const float*)d_in[2];
    const float* item_factors = (const float*)d_in[3];
    float*       out          = (float*)      d_out;

    int batch = in_sizes[0];                       // 16384
    int warps = batch / ELEMS_PER_WARP;            // 2048
    int blocks = warps / WARPS_PER_BLOCK;          // 512
    mf_dot_kernel<<<blocks, THREADS>>>(users, items, user_factors, item_factors, out);
}